// round 3
// baseline (speedup 1.0000x reference)
#include <cuda_runtime.h>
#include <cstdint>

#define Bb 2
#define Sq 2048
#define Dm 1024
#define Hh 16
#define Dk 64

// Scratch (allocation-free rule: __device__ globals)
__device__ __align__(16) float g_qh[(size_t)Bb*Hh*Sq*Dk];
__device__ __align__(16) float g_kh[(size_t)Bb*Hh*Sq*Dk];
__device__ __align__(16) float g_vh[(size_t)Bb*Hh*Sq*Dk];
__device__ __align__(16) float g_ao[(size_t)Bb*Sq*Dm];

// ---------------------------------------------------------------------------
// tf32 helpers
// ---------------------------------------------------------------------------
__device__ __forceinline__ uint32_t f2tf(float x) {
    uint32_t u;
    asm("cvt.rna.tf32.f32 %0, %1;" : "=r"(u) : "f"(x));
    return u;
}

__device__ __forceinline__ void mma_tf32(float c[4],
    uint32_t a0, uint32_t a1, uint32_t a2, uint32_t a3,
    uint32_t b0, uint32_t b1)
{
    asm volatile(
        "mma.sync.aligned.m16n8k8.row.col.f32.tf32.tf32.f32 "
        "{%0,%1,%2,%3}, {%4,%5,%6,%7}, {%8,%9}, {%0,%1,%2,%3};"
        : "+f"(c[0]), "+f"(c[1]), "+f"(c[2]), "+f"(c[3])
        : "r"(a0), "r"(a1), "r"(a2), "r"(a3), "r"(b0), "r"(b1));
}

// ============================================================================
// K1: fused Q/K/V projection (tf32 MMA). Y = X @ W^T + b.
// ============================================================================
__global__ __launch_bounds__(256) void proj_tc(
    const float* __restrict__ xq, const float* __restrict__ xk, const float* __restrict__ xv,
    const float* __restrict__ wq, const float* __restrict__ wk, const float* __restrict__ wv,
    const float* __restrict__ bq, const float* __restrict__ bk, const float* __restrict__ bv)
{
    const int which = blockIdx.z;
    const float* __restrict__ A    = which == 0 ? xq : (which == 1 ? xk : xv);
    const float* __restrict__ W    = which == 0 ? wq : (which == 1 ? wk : wv);
    const float* __restrict__ bias = which == 0 ? bq : (which == 1 ? bk : bv);
    float* __restrict__ dst        = which == 0 ? g_qh : (which == 1 ? g_kh : g_vh);

    __shared__ uint32_t As[16][136];   // [k][m]
    __shared__ uint32_t Bs[16][136];   // [k][n]

    const int tid = threadIdx.x;
    const int lane = tid & 31, wid = tid >> 5;
    const int wm = wid & 1, wn = wid >> 1;
    const int bm = blockIdx.y * 128, bn = blockIdx.x * 128;
    const int lr = lane >> 2, lc = lane & 3;

    float acc[4][4][4];
#pragma unroll
    for (int i = 0; i < 4; i++)
#pragma unroll
        for (int j = 0; j < 4; j++)
#pragma unroll
            for (int t = 0; t < 4; t++) acc[i][j][t] = 0.f;

    for (int k0 = 0; k0 < Dm; k0 += 16) {
#pragma unroll
        for (int t = 0; t < 2; t++) {
            int f = tid + t * 256;
            int row = f >> 2;
            int kq = (f & 3) << 2;
            float4 va = *(const float4*)(A + (size_t)(bm + row) * Dm + k0 + kq);
            As[kq + 0][row] = f2tf(va.x); As[kq + 1][row] = f2tf(va.y);
            As[kq + 2][row] = f2tf(va.z); As[kq + 3][row] = f2tf(va.w);
            float4 vb = *(const float4*)(W + (size_t)(bn + row) * Dm + k0 + kq);
            Bs[kq + 0][row] = f2tf(vb.x); Bs[kq + 1][row] = f2tf(vb.y);
            Bs[kq + 2][row] = f2tf(vb.z); Bs[kq + 3][row] = f2tf(vb.w);
        }
        __syncthreads();
#pragma unroll
        for (int ks = 0; ks < 16; ks += 8) {
            uint32_t af[4][4], bf[4][2];
#pragma unroll
            for (int mt = 0; mt < 4; mt++) {
                int rb = wm * 64 + mt * 16 + lr;
                af[mt][0] = As[ks + lc][rb];
                af[mt][1] = As[ks + lc][rb + 8];
                af[mt][2] = As[ks + 4 + lc][rb];
                af[mt][3] = As[ks + 4 + lc][rb + 8];
            }
#pragma unroll
            for (int nt = 0; nt < 4; nt++) {
                int nb = wn * 32 + nt * 8 + lr;
                bf[nt][0] = Bs[ks + lc][nb];
                bf[nt][1] = Bs[ks + 4 + lc][nb];
            }
#pragma unroll
            for (int mt = 0; mt < 4; mt++)
#pragma unroll
                for (int nt = 0; nt < 4; nt++)
                    mma_tf32(acc[mt][nt], af[mt][0], af[mt][1], af[mt][2], af[mt][3],
                             bf[nt][0], bf[nt][1]);
        }
        __syncthreads();
    }

#pragma unroll
    for (int mt = 0; mt < 4; mt++) {
#pragma unroll
        for (int nt = 0; nt < 4; nt++) {
            int col = bn + wn * 32 + nt * 8 + lc * 2;
            int h = col >> 6, d = col & 63;
            float b0 = bias[col], b1 = bias[col + 1];
#pragma unroll
            for (int half = 0; half < 2; half++) {
                int m = bm + wm * 64 + mt * 16 + lr + half * 8;
                int b = m >> 11;
                int s = m & (Sq - 1);
                float2 v;
                v.x = acc[mt][nt][half * 2 + 0] + b0;
                v.y = acc[mt][nt][half * 2 + 1] + b1;
                *(float2*)(dst + (((size_t)(b * Hh + h) * Sq + s) << 6) + d) = v;
            }
        }
    }
}

// ============================================================================
// K2: fused attention: scores + online softmax + write attn + AV.
// Block = 128 q-rows x one (b,h). 8 warps, each owns 16 q-rows.
// Pass A: stream K tiles (64 wide), track row max m and sum l online.
// Pass B: recompute scores, p = exp(s-m)/l, write p (via smem, coalesced),
//         accumulate O += P@V with tf32 MMA.
// smem ~104KB -> 2 blocks/SM.
// ============================================================================
#define BK 64

__global__ __launch_bounds__(256, 2) void attn_fused(
    const int* __restrict__ mask, float* __restrict__ sc)
{
    extern __shared__ uint32_t sh[];
    uint32_t (*Qs)[136] = (uint32_t(*)[136])sh;                     // [d64][q128+8]
    uint32_t (*Ks)[72]  = (uint32_t(*)[72])(sh + 64 * 136);         // [d64][k64+8]
    uint32_t (*Vs)[72]  = (uint32_t(*)[72])(sh + 64 * 136 + 64 * 72); // [k64][d64+8]
    float    (*Ps)[68]  = (float(*)[68])(sh + 64 * 136 + 2 * 64 * 72); // [q128][k64+4]

    const int bh = blockIdx.y;
    const int b = bh >> 4, h = bh & 15;
    const int q0 = blockIdx.x * 128;
    const float* qp    = g_qh + ((size_t)bh * Sq + q0) * Dk;
    const float* kbase = g_kh + (size_t)bh * Sq * Dk;
    const float* vbase = g_vh + (size_t)bh * Sq * Dk;

    const int tid = threadIdx.x;
    const int lane = tid & 31, w = tid >> 5;
    const int lr = lane >> 2, lc = lane & 3;
    const int r0 = 16 * w + lr;        // local q row (second row = r0+8)
    const int qg0 = q0 + r0;

    // load Q tile -> Qs[d][q]
#pragma unroll
    for (int t = 0; t < 8; t++) {
        int f = tid + t * 256;
        int row = f >> 4;
        int c4 = (f & 15) << 2;
        float4 v = *(const float4*)(qp + row * Dk + c4);
        Qs[c4 + 0][row] = f2tf(v.x); Qs[c4 + 1][row] = f2tf(v.y);
        Qs[c4 + 2][row] = f2tf(v.z); Qs[c4 + 3][row] = f2tf(v.w);
    }

    const int* mrow0 = mask + ((size_t)b * Sq + qg0) * Sq;
    const int* mrow1 = mrow0 + 8 * Sq;

    float m0 = -INFINITY, m1 = -INFINITY, l0 = 0.f, l1 = 0.f;
    float acc[8][4];

    // ---------------- PASS A: online max/sum ----------------
    for (int kt = 0; kt < Sq; kt += BK) {
        __syncthreads();
#pragma unroll
        for (int t = 0; t < 4; t++) {   // K tile: 64 tok x 64 d -> Ks[d][tok]
            int f = tid + t * 256;
            int row = f >> 4;
            int c4 = (f & 15) << 2;
            float4 v = *(const float4*)(kbase + (size_t)(kt + row) * Dk + c4);
            Ks[c4 + 0][row] = f2tf(v.x); Ks[c4 + 1][row] = f2tf(v.y);
            Ks[c4 + 2][row] = f2tf(v.z); Ks[c4 + 3][row] = f2tf(v.w);
        }
        __syncthreads();

#pragma unroll
        for (int nt = 0; nt < 8; nt++)
#pragma unroll
            for (int e = 0; e < 4; e++) acc[nt][e] = 0.f;

#pragma unroll
        for (int ks = 0; ks < 64; ks += 8) {
            uint32_t a0 = Qs[ks + lc][r0],     a1 = Qs[ks + lc][r0 + 8];
            uint32_t a2 = Qs[ks + 4 + lc][r0], a3 = Qs[ks + 4 + lc][r0 + 8];
#pragma unroll
            for (int nt = 0; nt < 8; nt++) {
                uint32_t b0 = Ks[ks + lc][nt * 8 + lr];
                uint32_t b1 = Ks[ks + 4 + lc][nt * 8 + lr];
                mma_tf32(acc[nt], a0, a1, a2, a3, b0, b1);
            }
        }

        float tm0 = -INFINITY, tm1 = -INFINITY;
#pragma unroll
        for (int nt = 0; nt < 8; nt++) {
            int kc = kt + nt * 8 + lc * 2;
            int2 ma = *(const int2*)(mrow0 + kc);
            int2 mb = *(const int2*)(mrow1 + kc);
            acc[nt][0] = (ma.x == 0) ? -1000000000.0f : acc[nt][0] * 0.125f;
            acc[nt][1] = (ma.y == 0) ? -1000000000.0f : acc[nt][1] * 0.125f;
            acc[nt][2] = (mb.x == 0) ? -1000000000.0f : acc[nt][2] * 0.125f;
            acc[nt][3] = (mb.y == 0) ? -1000000000.0f : acc[nt][3] * 0.125f;
            tm0 = fmaxf(tm0, fmaxf(acc[nt][0], acc[nt][1]));
            tm1 = fmaxf(tm1, fmaxf(acc[nt][2], acc[nt][3]));
        }
        tm0 = fmaxf(tm0, __shfl_xor_sync(0xffffffffu, tm0, 1));
        tm0 = fmaxf(tm0, __shfl_xor_sync(0xffffffffu, tm0, 2));
        tm1 = fmaxf(tm1, __shfl_xor_sync(0xffffffffu, tm1, 1));
        tm1 = fmaxf(tm1, __shfl_xor_sync(0xffffffffu, tm1, 2));
        float mn0 = fmaxf(m0, tm0), mn1 = fmaxf(m1, tm1);
        float ts0 = 0.f, ts1 = 0.f;
#pragma unroll
        for (int nt = 0; nt < 8; nt++) {
            ts0 += __expf(acc[nt][0] - mn0) + __expf(acc[nt][1] - mn0);
            ts1 += __expf(acc[nt][2] - mn1) + __expf(acc[nt][3] - mn1);
        }
        ts0 += __shfl_xor_sync(0xffffffffu, ts0, 1);
        ts0 += __shfl_xor_sync(0xffffffffu, ts0, 2);
        ts1 += __shfl_xor_sync(0xffffffffu, ts1, 1);
        ts1 += __shfl_xor_sync(0xffffffffu, ts1, 2);
        l0 = l0 * __expf(m0 - mn0) + ts0;
        l1 = l1 * __expf(m1 - mn1) + ts1;
        m0 = mn0; m1 = mn1;
    }

    const float inv0 = 1.0f / l0, inv1 = 1.0f / l1;

    float o_acc[8][4];
#pragma unroll
    for (int nt = 0; nt < 8; nt++)
#pragma unroll
        for (int e = 0; e < 4; e++) o_acc[nt][e] = 0.f;

    // ---------------- PASS B: recompute, normalize, write, AV ----------------
    for (int kt = 0; kt < Sq; kt += BK) {
        __syncthreads();
#pragma unroll
        for (int t = 0; t < 4; t++) {   // K tile
            int f = tid + t * 256;
            int row = f >> 4;
            int c4 = (f & 15) << 2;
            float4 v = *(const float4*)(kbase + (size_t)(kt + row) * Dk + c4);
            Ks[c4 + 0][row] = f2tf(v.x); Ks[c4 + 1][row] = f2tf(v.y);
            Ks[c4 + 2][row] = f2tf(v.z); Ks[c4 + 3][row] = f2tf(v.w);
        }
#pragma unroll
        for (int t = 0; t < 4; t++) {   // V tile: [tok][d]
            int f = tid + t * 256;
            int row = f >> 4;
            int c4 = (f & 15) << 2;
            float4 v = *(const float4*)(vbase + (size_t)(kt + row) * Dk + c4);
            Vs[row][c4 + 0] = f2tf(v.x); Vs[row][c4 + 1] = f2tf(v.y);
            Vs[row][c4 + 2] = f2tf(v.z); Vs[row][c4 + 3] = f2tf(v.w);
        }
        __syncthreads();

#pragma unroll
        for (int nt = 0; nt < 8; nt++)
#pragma unroll
            for (int e = 0; e < 4; e++) acc[nt][e] = 0.f;

#pragma unroll
        for (int ks = 0; ks < 64; ks += 8) {
            uint32_t a0 = Qs[ks + lc][r0],     a1 = Qs[ks + lc][r0 + 8];
            uint32_t a2 = Qs[ks + 4 + lc][r0], a3 = Qs[ks + 4 + lc][r0 + 8];
#pragma unroll
            for (int nt = 0; nt < 8; nt++) {
                uint32_t b0 = Ks[ks + lc][nt * 8 + lr];
                uint32_t b1 = Ks[ks + 4 + lc][nt * 8 + lr];
                mma_tf32(acc[nt], a0, a1, a2, a3, b0, b1);
            }
        }

        // normalize + stage into Ps
#pragma unroll
        for (int nt = 0; nt < 8; nt++) {
            int kc = kt + nt * 8 + lc * 2;
            int2 ma = *(const int2*)(mrow0 + kc);
            int2 mb = *(const int2*)(mrow1 + kc);
            float s00 = (ma.x == 0) ? -1000000000.0f : acc[nt][0] * 0.125f;
            float s01 = (ma.y == 0) ? -1000000000.0f : acc[nt][1] * 0.125f;
            float s10 = (mb.x == 0) ? -1000000000.0f : acc[nt][2] * 0.125f;
            float s11 = (mb.y == 0) ? -1000000000.0f : acc[nt][3] * 0.125f;
            int cl = nt * 8 + lc * 2;
            Ps[r0][cl]         = __expf(s00 - m0) * inv0;
            Ps[r0][cl + 1]     = __expf(s01 - m0) * inv0;
            Ps[r0 + 8][cl]     = __expf(s10 - m1) * inv1;
            Ps[r0 + 8][cl + 1] = __expf(s11 - m1) * inv1;
        }
        __syncthreads();

        // coalesced write of p tile to gmem
#pragma unroll
        for (int t = 0; t < 8; t++) {
            int f = tid + t * 256;
            int row = f >> 4;
            int c4 = (f & 15) << 2;
            float4 v = *(const float4*)&Ps[row][c4];
            *(float4*)(sc + (((size_t)(b * Sq + q0 + row)) * Hh + h) * Sq + kt + c4) = v;
        }

        // O += P @ V
#pragma unroll
        for (int ks = 0; ks < 64; ks += 8) {
            uint32_t a0 = f2tf(Ps[r0][ks + lc]);
            uint32_t a1 = f2tf(Ps[r0 + 8][ks + lc]);
            uint32_t a2 = f2tf(Ps[r0][ks + 4 + lc]);
            uint32_t a3 = f2tf(Ps[r0 + 8][ks + 4 + lc]);
#pragma unroll
            for (int nt = 0; nt < 8; nt++) {
                uint32_t b0 = Vs[ks + lc][nt * 8 + lr];
                uint32_t b1 = Vs[ks + 4 + lc][nt * 8 + lr];
                mma_tf32(o_acc[nt], a0, a1, a2, a3, b0, b1);
            }
        }
    }

    // epilogue: write O to g_ao in (b,s,D) layout
    float* orow0 = g_ao + (size_t)(b * Sq + qg0) * Dm + h * Dk;
    float* orow1 = orow0 + 8 * Dm;
#pragma unroll
    for (int nt = 0; nt < 8; nt++) {
        int d = nt * 8 + lc * 2;
        float2 v0 = make_float2(o_acc[nt][0], o_acc[nt][1]);
        float2 v1 = make_float2(o_acc[nt][2], o_acc[nt][3]);
        *(float2*)(orow0 + d) = v0;
        *(float2*)(orow1 + d) = v1;
    }
}

// ============================================================================
// K5: final projection out = g_ao @ Wo^T + bo  (tf32 MMA)
// ============================================================================
__global__ __launch_bounds__(256) void outproj_tc(
    const float* __restrict__ W, const float* __restrict__ bias, float* __restrict__ C)
{
    __shared__ uint32_t As[16][136];
    __shared__ uint32_t Bs[16][136];
    const int tid = threadIdx.x;
    const int lane = tid & 31, wid = tid >> 5;
    const int wm = wid & 1, wn = wid >> 1;
    const int bm = blockIdx.y * 128, bn = blockIdx.x * 128;
    const int lr = lane >> 2, lc = lane & 3;
    const float* __restrict__ A = g_ao;

    float acc[4][4][4];
#pragma unroll
    for (int i = 0; i < 4; i++)
#pragma unroll
        for (int j = 0; j < 4; j++)
#pragma unroll
            for (int t = 0; t < 4; t++) acc[i][j][t] = 0.f;

    for (int k0 = 0; k0 < Dm; k0 += 16) {
#pragma unroll
        for (int t = 0; t < 2; t++) {
            int f = tid + t * 256;
            int row = f >> 2;
            int kq = (f & 3) << 2;
            float4 va = *(const float4*)(A + (size_t)(bm + row) * Dm + k0 + kq);
            As[kq + 0][row] = f2tf(va.x); As[kq + 1][row] = f2tf(va.y);
            As[kq + 2][row] = f2tf(va.z); As[kq + 3][row] = f2tf(va.w);
            float4 vb = *(const float4*)(W + (size_t)(bn + row) * Dm + k0 + kq);
            Bs[kq + 0][row] = f2tf(vb.x); Bs[kq + 1][row] = f2tf(vb.y);
            Bs[kq + 2][row] = f2tf(vb.z); Bs[kq + 3][row] = f2tf(vb.w);
        }
        __syncthreads();
#pragma unroll
        for (int ks = 0; ks < 16; ks += 8) {
            uint32_t af[4][4], bf[4][2];
#pragma unroll
            for (int mt = 0; mt < 4; mt++) {
                int rb = wm * 64 + mt * 16 + lr;
                af[mt][0] = As[ks + lc][rb];
                af[mt][1] = As[ks + lc][rb + 8];
                af[mt][2] = As[ks + 4 + lc][rb];
                af[mt][3] = As[ks + 4 + lc][rb + 8];
            }
#pragma unroll
            for (int nt = 0; nt < 4; nt++) {
                int nb = wn * 32 + nt * 8 + lr;
                bf[nt][0] = Bs[ks + lc][nb];
                bf[nt][1] = Bs[ks + 4 + lc][nb];
            }
#pragma unroll
            for (int mt = 0; mt < 4; mt++)
#pragma unroll
                for (int nt = 0; nt < 4; nt++)
                    mma_tf32(acc[mt][nt], af[mt][0], af[mt][1], af[mt][2], af[mt][3],
                             bf[nt][0], bf[nt][1]);
        }
        __syncthreads();
    }

#pragma unroll
    for (int mt = 0; mt < 4; mt++) {
#pragma unroll
        for (int nt = 0; nt < 4; nt++) {
            int col = bn + wn * 32 + nt * 8 + lc * 2;
            float b0 = bias[col], b1 = bias[col + 1];
#pragma unroll
            for (int half = 0; half < 2; half++) {
                int m = bm + wm * 64 + mt * 16 + lr + half * 8;
                float2 v;
                v.x = acc[mt][nt][half * 2 + 0] + b0;
                v.y = acc[mt][nt][half * 2 + 1] + b1;
                *(float2*)(C + (size_t)m * Dm + col) = v;
            }
        }
    }
}

// ============================================================================
extern "C" void kernel_launch(void* const* d_in, const int* in_sizes, int n_in,
                              void* d_out, int out_size)
{
    const float* q    = (const float*)d_in[0];
    const float* k    = (const float*)d_in[1];
    const float* v    = (const float*)d_in[2];
    const int*   mask = (const int*)d_in[3];
    const float* Wq   = (const float*)d_in[4];
    const float* bq   = (const float*)d_in[5];
    const float* Wk   = (const float*)d_in[6];
    const float* bk   = (const float*)d_in[7];
    const float* Wv   = (const float*)d_in[8];
    const float* bv   = (const float*)d_in[9];
    const float* Wo   = (const float*)d_in[10];
    const float* bo   = (const float*)d_in[11];

    float* out = (float*)d_out;
    float* sc  = out + (size_t)Bb * Sq * Dm;   // scores_out region

    // smem: Qs 64*136*4 + Ks 64*72*4 + Vs 64*72*4 + Ps 128*68*4
    const int attn_smem = (64 * 136 + 2 * 64 * 72 + 128 * 68) * 4;  // 106496
    cudaFuncSetAttribute(attn_fused, cudaFuncAttributeMaxDynamicSharedMemorySize, attn_smem);

    dim3 gp(Dm / 128, (Bb * Sq) / 128, 3);
    proj_tc<<<gp, 256>>>(q, k, v, Wq, Wk, Wv, bq, bk, bv);

    dim3 ga(Sq / 128, Bb * Hh);
    attn_fused<<<ga, 256, attn_smem>>>(mask, sc);

    dim3 go(Dm / 128, (Bb * Sq) / 128);
    outproj_tc<<<go, 256>>>(Wo, bo, out);
}

// round 4
// speedup vs baseline: 1.1783x; 1.1783x over previous
#include <cuda_runtime.h>
#include <cstdint>

#define Bb 2
#define Sq 2048
#define Dm 1024
#define Hh 16
#define Dk 64

// Scratch (allocation-free rule: __device__ globals)
__device__ __align__(16) float g_qh[(size_t)Bb*Hh*Sq*Dk];
__device__ __align__(16) float g_kh[(size_t)Bb*Hh*Sq*Dk];
__device__ __align__(16) float g_vh[(size_t)Bb*Hh*Sq*Dk];
__device__ __align__(16) float g_ao[(size_t)Bb*Sq*Dm];

// ---------------------------------------------------------------------------
__device__ __forceinline__ uint32_t f2tf(float x) {
    uint32_t u;
    asm("cvt.rna.tf32.f32 %0, %1;" : "=r"(u) : "f"(x));
    return u;
}

__device__ __forceinline__ void mma_tf32(float c[4],
    uint32_t a0, uint32_t a1, uint32_t a2, uint32_t a3,
    uint32_t b0, uint32_t b1)
{
    asm volatile(
        "mma.sync.aligned.m16n8k8.row.col.f32.tf32.tf32.f32 "
        "{%0,%1,%2,%3}, {%4,%5,%6,%7}, {%8,%9}, {%0,%1,%2,%3};"
        : "+f"(c[0]), "+f"(c[1]), "+f"(c[2]), "+f"(c[3])
        : "r"(a0), "r"(a1), "r"(a2), "r"(a3), "r"(b0), "r"(b1));
}

// ============================================================================
// K1: fused Q/K/V projection (tf32 MMA, double-buffered).
// ============================================================================
__global__ __launch_bounds__(256) void proj_tc(
    const float* __restrict__ xq, const float* __restrict__ xk, const float* __restrict__ xv,
    const float* __restrict__ wq, const float* __restrict__ wk, const float* __restrict__ wv,
    const float* __restrict__ bq, const float* __restrict__ bk, const float* __restrict__ bv)
{
    const int which = blockIdx.z;
    const float* __restrict__ A    = which == 0 ? xq : (which == 1 ? xk : xv);
    const float* __restrict__ W    = which == 0 ? wq : (which == 1 ? wk : wv);
    const float* __restrict__ bias = which == 0 ? bq : (which == 1 ? bk : bv);
    float* __restrict__ dst        = which == 0 ? g_qh : (which == 1 ? g_kh : g_vh);

    __shared__ uint32_t As[2][16][136];
    __shared__ uint32_t Bs[2][16][136];

    const int tid = threadIdx.x;
    const int lane = tid & 31, wid = tid >> 5;
    const int wm = wid & 1, wn = wid >> 1;
    const int bm = blockIdx.y * 128, bn = blockIdx.x * 128;
    const int lr = lane >> 2, lc = lane & 3;

    const int row0 = tid >> 2,          kq0 = (tid & 3) << 2;
    const int row1 = (tid + 256) >> 2,  kq1 = ((tid + 256) & 3) << 2;

    float4 ra0, ra1, rb0, rb1;

#define PJ_LD(k0) do { \
    ra0 = *(const float4*)(A + (size_t)(bm + row0) * Dm + (k0) + kq0); \
    rb0 = *(const float4*)(W + (size_t)(bn + row0) * Dm + (k0) + kq0); \
    ra1 = *(const float4*)(A + (size_t)(bm + row1) * Dm + (k0) + kq1); \
    rb1 = *(const float4*)(W + (size_t)(bn + row1) * Dm + (k0) + kq1); \
} while (0)

#define PJ_ST(st) do { \
    As[st][kq0+0][row0]=f2tf(ra0.x); As[st][kq0+1][row0]=f2tf(ra0.y); \
    As[st][kq0+2][row0]=f2tf(ra0.z); As[st][kq0+3][row0]=f2tf(ra0.w); \
    Bs[st][kq0+0][row0]=f2tf(rb0.x); Bs[st][kq0+1][row0]=f2tf(rb0.y); \
    Bs[st][kq0+2][row0]=f2tf(rb0.z); Bs[st][kq0+3][row0]=f2tf(rb0.w); \
    As[st][kq1+0][row1]=f2tf(ra1.x); As[st][kq1+1][row1]=f2tf(ra1.y); \
    As[st][kq1+2][row1]=f2tf(ra1.z); As[st][kq1+3][row1]=f2tf(ra1.w); \
    Bs[st][kq1+0][row1]=f2tf(rb1.x); Bs[st][kq1+1][row1]=f2tf(rb1.y); \
    Bs[st][kq1+2][row1]=f2tf(rb1.z); Bs[st][kq1+3][row1]=f2tf(rb1.w); \
} while (0)

    float acc[4][4][4];
#pragma unroll
    for (int i = 0; i < 4; i++)
#pragma unroll
        for (int j = 0; j < 4; j++)
#pragma unroll
            for (int t = 0; t < 4; t++) acc[i][j][t] = 0.f;

    PJ_LD(0); PJ_ST(0); __syncthreads();

    for (int it = 0; it < 64; it++) {
        const int cur = it & 1;
        if (it < 63) PJ_LD((it + 1) * 16);
#pragma unroll
        for (int ks = 0; ks < 16; ks += 8) {
            uint32_t af[4][4], bf[4][2];
#pragma unroll
            for (int mt = 0; mt < 4; mt++) {
                int rb = wm * 64 + mt * 16 + lr;
                af[mt][0] = As[cur][ks + lc][rb];
                af[mt][1] = As[cur][ks + lc][rb + 8];
                af[mt][2] = As[cur][ks + 4 + lc][rb];
                af[mt][3] = As[cur][ks + 4 + lc][rb + 8];
            }
#pragma unroll
            for (int nt = 0; nt < 4; nt++) {
                int nb = wn * 32 + nt * 8 + lr;
                bf[nt][0] = Bs[cur][ks + lc][nb];
                bf[nt][1] = Bs[cur][ks + 4 + lc][nb];
            }
#pragma unroll
            for (int mt = 0; mt < 4; mt++)
#pragma unroll
                for (int nt = 0; nt < 4; nt++)
                    mma_tf32(acc[mt][nt], af[mt][0], af[mt][1], af[mt][2], af[mt][3],
                             bf[nt][0], bf[nt][1]);
        }
        if (it < 63) PJ_ST(cur ^ 1);
        __syncthreads();
    }

#pragma unroll
    for (int mt = 0; mt < 4; mt++) {
#pragma unroll
        for (int nt = 0; nt < 4; nt++) {
            int col = bn + wn * 32 + nt * 8 + lc * 2;
            int h = col >> 6, d = col & 63;
            float b0 = bias[col], b1 = bias[col + 1];
#pragma unroll
            for (int half = 0; half < 2; half++) {
                int m = bm + wm * 64 + mt * 16 + lr + half * 8;
                int b = m >> 11;
                int s = m & (Sq - 1);
                float2 v;
                v.x = acc[mt][nt][half * 2 + 0] + b0;
                v.y = acc[mt][nt][half * 2 + 1] + b1;
                *(float2*)(dst + (((size_t)(b * Hh + h) * Sq + s) << 6) + d) = v;
            }
        }
    }
#undef PJ_LD
#undef PJ_ST
}

// ============================================================================
// K2: fused attention, 512 threads, q-tile=256, double-buffered K/V.
// Pass A: online row max/sum.  Pass B: recompute, normalize, write p, PV.
// smem: Qs 64x264 + Ks 2x64x72 + Vs 2x64x72 + Ps 256x68  = 210944 B -> 1 CTA/SM
// ============================================================================
#define QT 256

__global__ __launch_bounds__(512, 1) void attn_fused(
    const int* __restrict__ mask, float* __restrict__ sc)
{
    extern __shared__ uint32_t sh[];
    uint32_t (*Qs)[264]     = (uint32_t(*)[264])sh;                       // [d][q]
    uint32_t (*Ks)[64][72]  = (uint32_t(*)[64][72])(sh + 64 * 264);       // [st][d][tok]
    uint32_t (*Vs)[64][72]  = (uint32_t(*)[64][72])(sh + 64 * 264 + 2*64*72); // [st][tok][d]
    float    (*Ps)[68]      = (float(*)[68])(sh + 64 * 264 + 4*64*72);    // [q][k]

    const int bh = blockIdx.y;
    const int b = bh >> 4, h = bh & 15;
    const int q0 = blockIdx.x * QT;
    const float* qp    = g_qh + ((size_t)bh * Sq + q0) * Dk;
    const float* kbase = g_kh + (size_t)bh * Sq * Dk;
    const float* vbase = g_vh + (size_t)bh * Sq * Dk;

    const int tid = threadIdx.x;
    const int lane = tid & 31, w = tid >> 5;          // 16 warps
    const int lr = lane >> 2, lc = lane & 3;
    const int r0 = 16 * w + lr;                        // local q row; second = r0+8
    const int qg0 = q0 + r0;

    // K/V tile load coords (64 tok x 64 d, 512 threads x 2 float4)
    const int rA = tid >> 4,            cA = (tid & 15) << 2;
    const int rB = (tid + 512) >> 4,    cB = ((tid + 512) & 15) << 2;

    float4 rk0, rk1, rv0, rv1;

#define AT_LDK(kt) do { \
    rk0 = *(const float4*)(kbase + (size_t)((kt) + rA) * Dk + cA); \
    rk1 = *(const float4*)(kbase + (size_t)((kt) + rB) * Dk + cB); \
} while (0)
#define AT_STK(st) do { \
    Ks[st][cA+0][rA]=f2tf(rk0.x); Ks[st][cA+1][rA]=f2tf(rk0.y); \
    Ks[st][cA+2][rA]=f2tf(rk0.z); Ks[st][cA+3][rA]=f2tf(rk0.w); \
    Ks[st][cB+0][rB]=f2tf(rk1.x); Ks[st][cB+1][rB]=f2tf(rk1.y); \
    Ks[st][cB+2][rB]=f2tf(rk1.z); Ks[st][cB+3][rB]=f2tf(rk1.w); \
} while (0)
#define AT_LDV(kt) do { \
    rv0 = *(const float4*)(vbase + (size_t)((kt) + rA) * Dk + cA); \
    rv1 = *(const float4*)(vbase + (size_t)((kt) + rB) * Dk + cB); \
} while (0)
#define AT_STV(st) do { \
    Vs[st][rA][cA+0]=f2tf(rv0.x); Vs[st][rA][cA+1]=f2tf(rv0.y); \
    Vs[st][rA][cA+2]=f2tf(rv0.z); Vs[st][rA][cA+3]=f2tf(rv0.w); \
    Vs[st][rB][cB+0]=f2tf(rv1.x); Vs[st][rB][cB+1]=f2tf(rv1.y); \
    Vs[st][rB][cB+2]=f2tf(rv1.z); Vs[st][rB][cB+3]=f2tf(rv1.w); \
} while (0)

    // load Q tile -> Qs[d][q]  (256 rows x 16 float4 = 4096 slots, 512 thr x 8)
#pragma unroll
    for (int t = 0; t < 8; t++) {
        int f = tid + t * 512;
        int row = f >> 4;
        int c4 = (f & 15) << 2;
        float4 v = *(const float4*)(qp + row * Dk + c4);
        Qs[c4 + 0][row] = f2tf(v.x); Qs[c4 + 1][row] = f2tf(v.y);
        Qs[c4 + 2][row] = f2tf(v.z); Qs[c4 + 3][row] = f2tf(v.w);
    }

    const int* mrow0 = mask + ((size_t)b * Sq + qg0) * Sq;
    const int* mrow1 = mrow0 + 8 * Sq;

    float m0 = -INFINITY, m1 = -INFINITY, l0 = 0.f, l1 = 0.f;
    float acc[8][4];

    // ---------------- PASS A ----------------
    AT_LDK(0); AT_STK(0); __syncthreads();

    for (int it = 0; it < Sq / 64; it++) {
        const int cur = it & 1;
        const int kt = it * 64;
        if (it < Sq / 64 - 1) AT_LDK(kt + 64);

#pragma unroll
        for (int nt = 0; nt < 8; nt++)
#pragma unroll
            for (int e = 0; e < 4; e++) acc[nt][e] = 0.f;

#pragma unroll
        for (int ks = 0; ks < 64; ks += 8) {
            uint32_t a0 = Qs[ks + lc][r0],     a1 = Qs[ks + lc][r0 + 8];
            uint32_t a2 = Qs[ks + 4 + lc][r0], a3 = Qs[ks + 4 + lc][r0 + 8];
#pragma unroll
            for (int nt = 0; nt < 8; nt++) {
                uint32_t b0 = Ks[cur][ks + lc][nt * 8 + lr];
                uint32_t b1 = Ks[cur][ks + 4 + lc][nt * 8 + lr];
                mma_tf32(acc[nt], a0, a1, a2, a3, b0, b1);
            }
        }

        float tm0 = -INFINITY, tm1 = -INFINITY;
#pragma unroll
        for (int nt = 0; nt < 8; nt++) {
            int kc = kt + nt * 8 + lc * 2;
            int2 ma = *(const int2*)(mrow0 + kc);
            int2 mb = *(const int2*)(mrow1 + kc);
            acc[nt][0] = (ma.x == 0) ? -1000000000.0f : acc[nt][0] * 0.125f;
            acc[nt][1] = (ma.y == 0) ? -1000000000.0f : acc[nt][1] * 0.125f;
            acc[nt][2] = (mb.x == 0) ? -1000000000.0f : acc[nt][2] * 0.125f;
            acc[nt][3] = (mb.y == 0) ? -1000000000.0f : acc[nt][3] * 0.125f;
            tm0 = fmaxf(tm0, fmaxf(acc[nt][0], acc[nt][1]));
            tm1 = fmaxf(tm1, fmaxf(acc[nt][2], acc[nt][3]));
        }
        tm0 = fmaxf(tm0, __shfl_xor_sync(0xffffffffu, tm0, 1));
        tm0 = fmaxf(tm0, __shfl_xor_sync(0xffffffffu, tm0, 2));
        tm1 = fmaxf(tm1, __shfl_xor_sync(0xffffffffu, tm1, 1));
        tm1 = fmaxf(tm1, __shfl_xor_sync(0xffffffffu, tm1, 2));
        float mn0 = fmaxf(m0, tm0), mn1 = fmaxf(m1, tm1);
        float ts0 = 0.f, ts1 = 0.f;
#pragma unroll
        for (int nt = 0; nt < 8; nt++) {
            ts0 += __expf(acc[nt][0] - mn0) + __expf(acc[nt][1] - mn0);
            ts1 += __expf(acc[nt][2] - mn1) + __expf(acc[nt][3] - mn1);
        }
        ts0 += __shfl_xor_sync(0xffffffffu, ts0, 1);
        ts0 += __shfl_xor_sync(0xffffffffu, ts0, 2);
        ts1 += __shfl_xor_sync(0xffffffffu, ts1, 1);
        ts1 += __shfl_xor_sync(0xffffffffu, ts1, 2);
        l0 = l0 * __expf(m0 - mn0) + ts0;
        l1 = l1 * __expf(m1 - mn1) + ts1;
        m0 = mn0; m1 = mn1;

        if (it < Sq / 64 - 1) AT_STK(cur ^ 1);
        __syncthreads();
    }

    const float inv0 = 1.0f / l0, inv1 = 1.0f / l1;

    float o_acc[8][4];
#pragma unroll
    for (int nt = 0; nt < 8; nt++)
#pragma unroll
        for (int e = 0; e < 4; e++) o_acc[nt][e] = 0.f;

    // ---------------- PASS B ----------------
    AT_LDK(0); AT_LDV(0); AT_STK(0); AT_STV(0); __syncthreads();

    for (int it = 0; it < Sq / 64; it++) {
        const int cur = it & 1;
        const int kt = it * 64;
        if (it < Sq / 64 - 1) { AT_LDK(kt + 64); AT_LDV(kt + 64); }

#pragma unroll
        for (int nt = 0; nt < 8; nt++)
#pragma unroll
            for (int e = 0; e < 4; e++) acc[nt][e] = 0.f;

#pragma unroll
        for (int ks = 0; ks < 64; ks += 8) {
            uint32_t a0 = Qs[ks + lc][r0],     a1 = Qs[ks + lc][r0 + 8];
            uint32_t a2 = Qs[ks + 4 + lc][r0], a3 = Qs[ks + 4 + lc][r0 + 8];
#pragma unroll
            for (int nt = 0; nt < 8; nt++) {
                uint32_t b0 = Ks[cur][ks + lc][nt * 8 + lr];
                uint32_t b1 = Ks[cur][ks + 4 + lc][nt * 8 + lr];
                mma_tf32(acc[nt], a0, a1, a2, a3, b0, b1);
            }
        }

        // normalize + stage into Ps
#pragma unroll
        for (int nt = 0; nt < 8; nt++) {
            int kc = kt + nt * 8 + lc * 2;
            int2 ma = *(const int2*)(mrow0 + kc);
            int2 mb = *(const int2*)(mrow1 + kc);
            float s00 = (ma.x == 0) ? -1000000000.0f : acc[nt][0] * 0.125f;
            float s01 = (ma.y == 0) ? -1000000000.0f : acc[nt][1] * 0.125f;
            float s10 = (mb.x == 0) ? -1000000000.0f : acc[nt][2] * 0.125f;
            float s11 = (mb.y == 0) ? -1000000000.0f : acc[nt][3] * 0.125f;
            int cl = nt * 8 + lc * 2;
            Ps[r0][cl]         = __expf(s00 - m0) * inv0;
            Ps[r0][cl + 1]     = __expf(s01 - m0) * inv0;
            Ps[r0 + 8][cl]     = __expf(s10 - m1) * inv1;
            Ps[r0 + 8][cl + 1] = __expf(s11 - m1) * inv1;
        }
        __syncthreads();

        // coalesced write of p tile (256 rows x 64 cols)
#pragma unroll
        for (int t = 0; t < 8; t++) {
            int f = tid + t * 512;
            int row = f >> 4;
            int c4 = (f & 15) << 2;
            float4 v = *(const float4*)&Ps[row][c4];
            *(float4*)(sc + (((size_t)(b * Sq + q0 + row)) * Hh + h) * Sq + kt + c4) = v;
        }

        // O += P @ V  (P fed as raw fp32 bits -> HW tf32 truncation)
#pragma unroll
        for (int ks = 0; ks < 64; ks += 8) {
            uint32_t a0 = __float_as_uint(Ps[r0][ks + lc]);
            uint32_t a1 = __float_as_uint(Ps[r0 + 8][ks + lc]);
            uint32_t a2 = __float_as_uint(Ps[r0][ks + 4 + lc]);
            uint32_t a3 = __float_as_uint(Ps[r0 + 8][ks + 4 + lc]);
#pragma unroll
            for (int nt = 0; nt < 8; nt++) {
                uint32_t b0 = Vs[cur][ks + lc][nt * 8 + lr];
                uint32_t b1 = Vs[cur][ks + 4 + lc][nt * 8 + lr];
                mma_tf32(o_acc[nt], a0, a1, a2, a3, b0, b1);
            }
        }

        if (it < Sq / 64 - 1) { AT_STK(cur ^ 1); AT_STV(cur ^ 1); }
        __syncthreads();
    }

    // epilogue: write O to g_ao in (b,s,D) layout
    float* orow0 = g_ao + (size_t)(b * Sq + qg0) * Dm + h * Dk;
    float* orow1 = orow0 + 8 * Dm;
#pragma unroll
    for (int nt = 0; nt < 8; nt++) {
        int d = nt * 8 + lc * 2;
        *(float2*)(orow0 + d) = make_float2(o_acc[nt][0], o_acc[nt][1]);
        *(float2*)(orow1 + d) = make_float2(o_acc[nt][2], o_acc[nt][3]);
    }
#undef AT_LDK
#undef AT_STK
#undef AT_LDV
#undef AT_STV
}

// ============================================================================
// K5: final projection out = g_ao @ Wo^T + bo  (tf32 MMA, double-buffered)
// ============================================================================
__global__ __launch_bounds__(256) void outproj_tc(
    const float* __restrict__ W, const float* __restrict__ bias, float* __restrict__ C)
{
    __shared__ uint32_t As[2][16][136];
    __shared__ uint32_t Bs[2][16][136];
    const int tid = threadIdx.x;
    const int lane = tid & 31, wid = tid >> 5;
    const int wm = wid & 1, wn = wid >> 1;
    const int bm = blockIdx.y * 128, bn = blockIdx.x * 128;
    const int lr = lane >> 2, lc = lane & 3;
    const float* __restrict__ A = g_ao;

    const int row0 = tid >> 2,          kq0 = (tid & 3) << 2;
    const int row1 = (tid + 256) >> 2,  kq1 = ((tid + 256) & 3) << 2;

    float4 ra0, ra1, rb0, rb1;

#define OP_LD(k0) do { \
    ra0 = *(const float4*)(A + (size_t)(bm + row0) * Dm + (k0) + kq0); \
    rb0 = *(const float4*)(W + (size_t)(bn + row0) * Dm + (k0) + kq0); \
    ra1 = *(const float4*)(A + (size_t)(bm + row1) * Dm + (k0) + kq1); \
    rb1 = *(const float4*)(W + (size_t)(bn + row1) * Dm + (k0) + kq1); \
} while (0)

#define OP_ST(st) do { \
    As[st][kq0+0][row0]=f2tf(ra0.x); As[st][kq0+1][row0]=f2tf(ra0.y); \
    As[st][kq0+2][row0]=f2tf(ra0.z); As[st][kq0+3][row0]=f2tf(ra0.w); \
    Bs[st][kq0+0][row0]=f2tf(rb0.x); Bs[st][kq0+1][row0]=f2tf(rb0.y); \
    Bs[st][kq0+2][row0]=f2tf(rb0.z); Bs[st][kq0+3][row0]=f2tf(rb0.w); \
    As[st][kq1+0][row1]=f2tf(ra1.x); As[st][kq1+1][row1]=f2tf(ra1.y); \
    As[st][kq1+2][row1]=f2tf(ra1.z); As[st][kq1+3][row1]=f2tf(ra1.w); \
    Bs[st][kq1+0][row1]=f2tf(rb1.x); Bs[st][kq1+1][row1]=f2tf(rb1.y); \
    Bs[st][kq1+2][row1]=f2tf(rb1.z); Bs[st][kq1+3][row1]=f2tf(rb1.w); \
} while (0)

    float acc[4][4][4];
#pragma unroll
    for (int i = 0; i < 4; i++)
#pragma unroll
        for (int j = 0; j < 4; j++)
#pragma unroll
            for (int t = 0; t < 4; t++) acc[i][j][t] = 0.f;

    OP_LD(0); OP_ST(0); __syncthreads();

    for (int it = 0; it < 64; it++) {
        const int cur = it & 1;
        if (it < 63) OP_LD((it + 1) * 16);
#pragma unroll
        for (int ks = 0; ks < 16; ks += 8) {
            uint32_t af[4][4], bf[4][2];
#pragma unroll
            for (int mt = 0; mt < 4; mt++) {
                int rb = wm * 64 + mt * 16 + lr;
                af[mt][0] = As[cur][ks + lc][rb];
                af[mt][1] = As[cur][ks + lc][rb + 8];
                af[mt][2] = As[cur][ks + 4 + lc][rb];
                af[mt][3] = As[cur][ks + 4 + lc][rb + 8];
            }
#pragma unroll
            for (int nt = 0; nt < 4; nt++) {
                int nb = wn * 32 + nt * 8 + lr;
                bf[nt][0] = Bs[cur][ks + lc][nb];
                bf[nt][1] = Bs[cur][ks + 4 + lc][nb];
            }
#pragma unroll
            for (int mt = 0; mt < 4; mt++)
#pragma unroll
                for (int nt = 0; nt < 4; nt++)
                    mma_tf32(acc[mt][nt], af[mt][0], af[mt][1], af[mt][2], af[mt][3],
                             bf[nt][0], bf[nt][1]);
        }
        if (it < 63) OP_ST(cur ^ 1);
        __syncthreads();
    }

#pragma unroll
    for (int mt = 0; mt < 4; mt++) {
#pragma unroll
        for (int nt = 0; nt < 4; nt++) {
            int col = bn + wn * 32 + nt * 8 + lc * 2;
            float b0 = bias[col], b1 = bias[col + 1];
#pragma unroll
            for (int half = 0; half < 2; half++) {
                int m = bm + wm * 64 + mt * 16 + lr + half * 8;
                float2 v;
                v.x = acc[mt][nt][half * 2 + 0] + b0;
                v.y = acc[mt][nt][half * 2 + 1] + b1;
                *(float2*)(C + (size_t)m * Dm + col) = v;
            }
        }
    }
#undef OP_LD
#undef OP_ST
}

// ============================================================================
extern "C" void kernel_launch(void* const* d_in, const int* in_sizes, int n_in,
                              void* d_out, int out_size)
{
    const float* q    = (const float*)d_in[0];
    const float* k    = (const float*)d_in[1];
    const float* v    = (const float*)d_in[2];
    const int*   mask = (const int*)d_in[3];
    const float* Wq   = (const float*)d_in[4];
    const float* bq   = (const float*)d_in[5];
    const float* Wk   = (const float*)d_in[6];
    const float* bk   = (const float*)d_in[7];
    const float* Wv   = (const float*)d_in[8];
    const float* bv   = (const float*)d_in[9];
    const float* Wo   = (const float*)d_in[10];
    const float* bo   = (const float*)d_in[11];

    float* out = (float*)d_out;
    float* sc  = out + (size_t)Bb * Sq * Dm;   // scores_out region

    // smem: Qs 64*264 + Ks 2*64*72 + Vs 2*64*72 + Ps 256*68  (words) * 4
    const int attn_smem = (64 * 264 + 4 * 64 * 72 + 256 * 68) * 4;  // 210944
    cudaFuncSetAttribute(attn_fused, cudaFuncAttributeMaxDynamicSharedMemorySize, attn_smem);

    dim3 gp(Dm / 128, (Bb * Sq) / 128, 3);
    proj_tc<<<gp, 256>>>(q, k, v, Wq, Wk, Wv, bq, bk, bv);

    dim3 ga(Sq / QT, Bb * Hh);
    attn_fused<<<ga, 512, attn_smem>>>(mask, sc);

    dim3 go(Dm / 128, (Bb * Sq) / 128);
    outproj_tc<<<go, 256>>>(Wo, bo, out);
}

// round 5
// speedup vs baseline: 1.4342x; 1.2172x over previous
#include <cuda_runtime.h>
#include <cstdint>

#define Bb 2
#define Sq 2048
#define Dm 1024
#define Hh 16
#define Dk 64

// Scratch (allocation-free rule: __device__ globals)
__device__ __align__(16) float g_qh[(size_t)Bb*Hh*Sq*Dk];
__device__ __align__(16) float g_kh[(size_t)Bb*Hh*Sq*Dk];
__device__ __align__(16) float g_vh[(size_t)Bb*Hh*Sq*Dk];
__device__ __align__(16) float g_ao[(size_t)Bb*Sq*Dm];
__device__ __align__(16) float g_linv[(size_t)Bb*Sq*Hh];

// ---------------------------------------------------------------------------
__device__ __forceinline__ uint32_t f2tf(float x) {
    uint32_t u;
    asm("cvt.rna.tf32.f32 %0, %1;" : "=r"(u) : "f"(x));
    return u;
}

__device__ __forceinline__ void mma_tf32(float c[4],
    uint32_t a0, uint32_t a1, uint32_t a2, uint32_t a3,
    uint32_t b0, uint32_t b1)
{
    asm volatile(
        "mma.sync.aligned.m16n8k8.row.col.f32.tf32.tf32.f32 "
        "{%0,%1,%2,%3}, {%4,%5,%6,%7}, {%8,%9}, {%0,%1,%2,%3};"
        : "+f"(c[0]), "+f"(c[1]), "+f"(c[2]), "+f"(c[3])
        : "r"(a0), "r"(a1), "r"(a2), "r"(a3), "r"(b0), "r"(b1));
}

__device__ __forceinline__ uint4 tf4(float4 v) {
    uint4 u;
    u.x = f2tf(v.x); u.y = f2tf(v.y); u.z = f2tf(v.z); u.w = f2tf(v.w);
    return u;
}

// ============================================================================
// K1: fused Q/K/V projection (tf32 MMA, double-buffered, row-major smem).
// ============================================================================
__global__ __launch_bounds__(256) void proj_tc(
    const float* __restrict__ xq, const float* __restrict__ xk, const float* __restrict__ xv,
    const float* __restrict__ wq, const float* __restrict__ wk, const float* __restrict__ wv,
    const float* __restrict__ bq, const float* __restrict__ bk, const float* __restrict__ bv)
{
    const int which = blockIdx.z;
    const float* __restrict__ A    = which == 0 ? xq : (which == 1 ? xk : xv);
    const float* __restrict__ W    = which == 0 ? wq : (which == 1 ? wk : wv);
    const float* __restrict__ bias = which == 0 ? bq : (which == 1 ? bk : bv);
    float* __restrict__ dst        = which == 0 ? g_qh : (which == 1 ? g_kh : g_vh);

    __shared__ uint32_t As[2][128][20];   // [row m][k], pad 16->20
    __shared__ uint32_t Bs[2][128][20];   // [row n][k]

    const int tid = threadIdx.x;
    const int lane = tid & 31, wid = tid >> 5;
    const int wm = wid & 1, wn = wid >> 1;
    const int bm = blockIdx.y * 128, bn = blockIdx.x * 128;
    const int lr = lane >> 2, lc = lane & 3;

    const int row0 = tid >> 2,          kq0 = (tid & 3) << 2;
    const int row1 = (tid + 256) >> 2,  kq1 = ((tid + 256) & 3) << 2;

    float4 ra0, ra1, rb0, rb1;

#define PJ_LD(k0) do { \
    ra0 = *(const float4*)(A + (size_t)(bm + row0) * Dm + (k0) + kq0); \
    rb0 = *(const float4*)(W + (size_t)(bn + row0) * Dm + (k0) + kq0); \
    ra1 = *(const float4*)(A + (size_t)(bm + row1) * Dm + (k0) + kq1); \
    rb1 = *(const float4*)(W + (size_t)(bn + row1) * Dm + (k0) + kq1); \
} while (0)

#define PJ_ST(st) do { \
    *(uint4*)&As[st][row0][kq0] = tf4(ra0); \
    *(uint4*)&Bs[st][row0][kq0] = tf4(rb0); \
    *(uint4*)&As[st][row1][kq1] = tf4(ra1); \
    *(uint4*)&Bs[st][row1][kq1] = tf4(rb1); \
} while (0)

    float acc[4][4][4];
#pragma unroll
    for (int i = 0; i < 4; i++)
#pragma unroll
        for (int j = 0; j < 4; j++)
#pragma unroll
            for (int t = 0; t < 4; t++) acc[i][j][t] = 0.f;

    PJ_LD(0); PJ_ST(0); __syncthreads();

    for (int it = 0; it < 64; it++) {
        const int cur = it & 1;
        if (it < 63) PJ_LD((it + 1) * 16);
#pragma unroll
        for (int ks = 0; ks < 16; ks += 8) {
            uint32_t af[4][4], bf[4][2];
#pragma unroll
            for (int mt = 0; mt < 4; mt++) {
                int rb = wm * 64 + mt * 16 + lr;
                af[mt][0] = As[cur][rb][ks + lc];
                af[mt][1] = As[cur][rb + 8][ks + lc];
                af[mt][2] = As[cur][rb][ks + 4 + lc];
                af[mt][3] = As[cur][rb + 8][ks + 4 + lc];
            }
#pragma unroll
            for (int nt = 0; nt < 4; nt++) {
                int nb = wn * 32 + nt * 8 + lr;
                bf[nt][0] = Bs[cur][nb][ks + lc];
                bf[nt][1] = Bs[cur][nb][ks + 4 + lc];
            }
#pragma unroll
            for (int mt = 0; mt < 4; mt++)
#pragma unroll
                for (int nt = 0; nt < 4; nt++)
                    mma_tf32(acc[mt][nt], af[mt][0], af[mt][1], af[mt][2], af[mt][3],
                             bf[nt][0], bf[nt][1]);
        }
        if (it < 63) PJ_ST(cur ^ 1);
        __syncthreads();
    }

#pragma unroll
    for (int mt = 0; mt < 4; mt++) {
#pragma unroll
        for (int nt = 0; nt < 4; nt++) {
            int col = bn + wn * 32 + nt * 8 + lc * 2;
            int h = col >> 6, d = col & 63;
            float b0 = bias[col], b1 = bias[col + 1];
#pragma unroll
            for (int half = 0; half < 2; half++) {
                int m = bm + wm * 64 + mt * 16 + lr + half * 8;
                int b = m >> 11;
                int s = m & (Sq - 1);
                float2 v;
                v.x = acc[mt][nt][half * 2 + 0] + b0;
                v.y = acc[mt][nt][half * 2 + 1] + b1;
                *(float2*)(dst + (((size_t)(b * Hh + h) * Sq + s) << 6) + d) = v;
            }
        }
    }
#undef PJ_LD
#undef PJ_ST
}

// ============================================================================
// K2: fused attention, single pass, no max-subtraction (scores are small:
// softmax is shift-invariant; fp32 exp safe for |s| < 80).
// Writes UNNORMALIZED exp(s) to the scores region and 1/rowsum to g_linv;
// O accumulated unnormalized and scaled in the epilogue.
// 512 threads, q-tile 256, double-buffered K/V, row-major conflict-free smem.
// ============================================================================
#define QT 256

__global__ __launch_bounds__(512, 1) void attn_fused(
    const int* __restrict__ mask, float* __restrict__ sc)
{
    extern __shared__ uint32_t sh[];
    uint32_t (*Qs)[68]     = (uint32_t(*)[68])sh;                    // [q256][d]
    uint32_t (*Ks)[64][68] = (uint32_t(*)[64][68])(sh + 17408);      // [st][tok][d]
    uint32_t (*Vs)[64][72] = (uint32_t(*)[64][72])(sh + 17408 + 8704); // [st][tok][d]
    float    (*Ps)[68]     = (float(*)[68])(sh + 17408 + 8704 + 9216); // [q][k]

    const int bh = blockIdx.y;
    const int b = bh >> 4, h = bh & 15;
    const int q0 = blockIdx.x * QT;
    const float* qp    = g_qh + ((size_t)bh * Sq + q0) * Dk;
    const float* kbase = g_kh + (size_t)bh * Sq * Dk;
    const float* vbase = g_vh + (size_t)bh * Sq * Dk;

    const int tid = threadIdx.x;
    const int lane = tid & 31, w = tid >> 5;          // 16 warps
    const int lr = lane >> 2, lc = lane & 3;
    const int r0 = 16 * w + lr;                        // local q row; second = r0+8
    const int qg0 = q0 + r0;

    const int rA = tid >> 4, cA = (tid & 15) << 2;    // K/V tile: 64x64, 2 f4/thread
    const int rB = rA + 32;

    float4 rk0, rk1, rv0, rv1;

#define AT_LDK(kt) do { \
    rk0 = *(const float4*)(kbase + (size_t)((kt) + rA) * Dk + cA); \
    rk1 = *(const float4*)(kbase + (size_t)((kt) + rB) * Dk + cA); \
} while (0)
#define AT_STK(st) do { \
    *(uint4*)&Ks[st][rA][cA] = tf4(rk0); \
    *(uint4*)&Ks[st][rB][cA] = tf4(rk1); \
} while (0)
#define AT_LDV(kt) do { \
    rv0 = *(const float4*)(vbase + (size_t)((kt) + rA) * Dk + cA); \
    rv1 = *(const float4*)(vbase + (size_t)((kt) + rB) * Dk + cA); \
} while (0)
#define AT_STV(st) do { \
    *(uint4*)&Vs[st][rA][cA] = tf4(rv0); \
    *(uint4*)&Vs[st][rB][cA] = tf4(rv1); \
} while (0)

    // load Q tile -> Qs[q][d]  (256 rows x 16 f4 slots, 512 thr x 8)
#pragma unroll
    for (int t = 0; t < 8; t++) {
        int f = tid + t * 512;
        int row = f >> 4;
        int c4 = (f & 15) << 2;
        *(uint4*)&Qs[row][c4] = tf4(*(const float4*)(qp + row * Dk + c4));
    }

    const int* mrow0 = mask + ((size_t)b * Sq + qg0) * Sq;
    const int* mrow1 = mrow0 + 8 * Sq;

    float lsum0 = 0.f, lsum1 = 0.f;
    float o_acc[8][4];
#pragma unroll
    for (int nt = 0; nt < 8; nt++)
#pragma unroll
        for (int e = 0; e < 4; e++) o_acc[nt][e] = 0.f;

    AT_LDK(0); AT_LDV(0); AT_STK(0); AT_STV(0); __syncthreads();

    for (int it = 0; it < Sq / 64; it++) {
        const int cur = it & 1;
        const int kt = it * 64;
        if (it < Sq / 64 - 1) { AT_LDK(kt + 64); AT_LDV(kt + 64); }

        float acc[8][4];
#pragma unroll
        for (int nt = 0; nt < 8; nt++)
#pragma unroll
            for (int e = 0; e < 4; e++) acc[nt][e] = 0.f;

        // QK^T
#pragma unroll
        for (int ks = 0; ks < 64; ks += 8) {
            uint32_t a0 = Qs[r0][ks + lc],     a1 = Qs[r0 + 8][ks + lc];
            uint32_t a2 = Qs[r0][ks + 4 + lc], a3 = Qs[r0 + 8][ks + 4 + lc];
#pragma unroll
            for (int nt = 0; nt < 8; nt++) {
                uint32_t b0 = Ks[cur][nt * 8 + lr][ks + lc];
                uint32_t b1 = Ks[cur][nt * 8 + lr][ks + 4 + lc];
                mma_tf32(acc[nt], a0, a1, a2, a3, b0, b1);
            }
        }

        // exp (no max), mask -> 0, accumulate row sums, stage into Ps
#pragma unroll
        for (int nt = 0; nt < 8; nt++) {
            int kc = kt + nt * 8 + lc * 2;
            int2 ma = *(const int2*)(mrow0 + kc);
            int2 mb = *(const int2*)(mrow1 + kc);
            float e00 = (ma.x == 0) ? 0.f : __expf(acc[nt][0] * 0.125f);
            float e01 = (ma.y == 0) ? 0.f : __expf(acc[nt][1] * 0.125f);
            float e10 = (mb.x == 0) ? 0.f : __expf(acc[nt][2] * 0.125f);
            float e11 = (mb.y == 0) ? 0.f : __expf(acc[nt][3] * 0.125f);
            lsum0 += e00 + e01;
            lsum1 += e10 + e11;
            int cl = nt * 8 + lc * 2;
            Ps[r0][cl]         = e00;
            Ps[r0][cl + 1]     = e01;
            Ps[r0 + 8][cl]     = e10;
            Ps[r0 + 8][cl + 1] = e11;
        }
        __syncthreads();

        // coalesced write of unnormalized E tile (256 rows x 64 cols)
#pragma unroll
        for (int t = 0; t < 8; t++) {
            int f = tid + t * 512;
            int row = f >> 4;
            int c4 = (f & 15) << 2;
            float4 v = *(const float4*)&Ps[row][c4];
            *(float4*)(sc + (((size_t)(b * Sq + q0 + row)) * Hh + h) * Sq + kt + c4) = v;
        }

        // O += E @ V  (E fed as raw fp32 bits -> HW tf32 truncation)
#pragma unroll
        for (int ks = 0; ks < 64; ks += 8) {
            uint32_t a0 = __float_as_uint(Ps[r0][ks + lc]);
            uint32_t a1 = __float_as_uint(Ps[r0 + 8][ks + lc]);
            uint32_t a2 = __float_as_uint(Ps[r0][ks + 4 + lc]);
            uint32_t a3 = __float_as_uint(Ps[r0 + 8][ks + 4 + lc]);
#pragma unroll
            for (int nt = 0; nt < 8; nt++) {
                uint32_t b0 = Vs[cur][ks + lc][nt * 8 + lr];
                uint32_t b1 = Vs[cur][ks + 4 + lc][nt * 8 + lr];
                mma_tf32(o_acc[nt], a0, a1, a2, a3, b0, b1);
            }
        }

        if (it < Sq / 64 - 1) { AT_STK(cur ^ 1); AT_STV(cur ^ 1); }
        __syncthreads();
    }

    // reduce row sums over the 4 lc lanes
    lsum0 += __shfl_xor_sync(0xffffffffu, lsum0, 1);
    lsum0 += __shfl_xor_sync(0xffffffffu, lsum0, 2);
    lsum1 += __shfl_xor_sync(0xffffffffu, lsum1, 1);
    lsum1 += __shfl_xor_sync(0xffffffffu, lsum1, 2);
    const float inv0 = 1.0f / lsum0, inv1 = 1.0f / lsum1;

    if (lc == 0) {
        g_linv[((size_t)(b * Sq + qg0)) * Hh + h]     = inv0;
        g_linv[((size_t)(b * Sq + qg0 + 8)) * Hh + h] = inv1;
    }

    // epilogue: write O (scaled) to g_ao in (b,s,D) layout
    float* orow0 = g_ao + (size_t)(b * Sq + qg0) * Dm + h * Dk;
    float* orow1 = orow0 + 8 * Dm;
#pragma unroll
    for (int nt = 0; nt < 8; nt++) {
        int d = nt * 8 + lc * 2;
        *(float2*)(orow0 + d) = make_float2(o_acc[nt][0] * inv0, o_acc[nt][1] * inv0);
        *(float2*)(orow1 + d) = make_float2(o_acc[nt][2] * inv1, o_acc[nt][3] * inv1);
    }
#undef AT_LDK
#undef AT_STK
#undef AT_LDV
#undef AT_STV
}

// ============================================================================
// K3: normalize scores rows: sc[row][:] *= linv[row]. Pure streaming.
// ============================================================================
__global__ __launch_bounds__(512) void norm_rows(
    float* __restrict__ sc, const float* __restrict__ linv)
{
    const int r = blockIdx.x;
    const float s = linv[r];
    float4* p = (float4*)(sc + (size_t)r * Sq);
    float4 v = p[threadIdx.x];
    v.x *= s; v.y *= s; v.z *= s; v.w *= s;
    p[threadIdx.x] = v;
}

// ============================================================================
// K4: final projection out = g_ao @ Wo^T + bo  (tf32 MMA, double-buffered)
// ============================================================================
__global__ __launch_bounds__(256) void outproj_tc(
    const float* __restrict__ W, const float* __restrict__ bias, float* __restrict__ C)
{
    __shared__ uint32_t As[2][128][20];
    __shared__ uint32_t Bs[2][128][20];
    const int tid = threadIdx.x;
    const int lane = tid & 31, wid = tid >> 5;
    const int wm = wid & 1, wn = wid >> 1;
    const int bm = blockIdx.y * 128, bn = blockIdx.x * 128;
    const int lr = lane >> 2, lc = lane & 3;
    const float* __restrict__ A = g_ao;

    const int row0 = tid >> 2,          kq0 = (tid & 3) << 2;
    const int row1 = (tid + 256) >> 2,  kq1 = ((tid + 256) & 3) << 2;

    float4 ra0, ra1, rb0, rb1;

#define OP_LD(k0) do { \
    ra0 = *(const float4*)(A + (size_t)(bm + row0) * Dm + (k0) + kq0); \
    rb0 = *(const float4*)(W + (size_t)(bn + row0) * Dm + (k0) + kq0); \
    ra1 = *(const float4*)(A + (size_t)(bm + row1) * Dm + (k0) + kq1); \
    rb1 = *(const float4*)(W + (size_t)(bn + row1) * Dm + (k0) + kq1); \
} while (0)

#define OP_ST(st) do { \
    *(uint4*)&As[st][row0][kq0] = tf4(ra0); \
    *(uint4*)&Bs[st][row0][kq0] = tf4(rb0); \
    *(uint4*)&As[st][row1][kq1] = tf4(ra1); \
    *(uint4*)&Bs[st][row1][kq1] = tf4(rb1); \
} while (0)

    float acc[4][4][4];
#pragma unroll
    for (int i = 0; i < 4; i++)
#pragma unroll
        for (int j = 0; j < 4; j++)
#pragma unroll
            for (int t = 0; t < 4; t++) acc[i][j][t] = 0.f;

    OP_LD(0); OP_ST(0); __syncthreads();

    for (int it = 0; it < 64; it++) {
        const int cur = it & 1;
        if (it < 63) OP_LD((it + 1) * 16);
#pragma unroll
        for (int ks = 0; ks < 16; ks += 8) {
            uint32_t af[4][4], bf[4][2];
#pragma unroll
            for (int mt = 0; mt < 4; mt++) {
                int rb = wm * 64 + mt * 16 + lr;
                af[mt][0] = As[cur][rb][ks + lc];
                af[mt][1] = As[cur][rb + 8][ks + lc];
                af[mt][2] = As[cur][rb][ks + 4 + lc];
                af[mt][3] = As[cur][rb + 8][ks + 4 + lc];
            }
#pragma unroll
            for (int nt = 0; nt < 4; nt++) {
                int nb = wn * 32 + nt * 8 + lr;
                bf[nt][0] = Bs[cur][nb][ks + lc];
                bf[nt][1] = Bs[cur][nb][ks + 4 + lc];
            }
#pragma unroll
            for (int mt = 0; mt < 4; mt++)
#pragma unroll
                for (int nt = 0; nt < 4; nt++)
                    mma_tf32(acc[mt][nt], af[mt][0], af[mt][1], af[mt][2], af[mt][3],
                             bf[nt][0], bf[nt][1]);
        }
        if (it < 63) OP_ST(cur ^ 1);
        __syncthreads();
    }

#pragma unroll
    for (int mt = 0; mt < 4; mt++) {
#pragma unroll
        for (int nt = 0; nt < 4; nt++) {
            int col = bn + wn * 32 + nt * 8 + lc * 2;
            float b0 = bias[col], b1 = bias[col + 1];
#pragma unroll
            for (int half = 0; half < 2; half++) {
                int m = bm + wm * 64 + mt * 16 + lr + half * 8;
                float2 v;
                v.x = acc[mt][nt][half * 2 + 0] + b0;
                v.y = acc[mt][nt][half * 2 + 1] + b1;
                *(float2*)(C + (size_t)m * Dm + col) = v;
            }
        }
    }
#undef OP_LD
#undef OP_ST
}

// ============================================================================
extern "C" void kernel_launch(void* const* d_in, const int* in_sizes, int n_in,
                              void* d_out, int out_size)
{
    const float* q    = (const float*)d_in[0];
    const float* k    = (const float*)d_in[1];
    const float* v    = (const float*)d_in[2];
    const int*   mask = (const int*)d_in[3];
    const float* Wq   = (const float*)d_in[4];
    const float* bq   = (const float*)d_in[5];
    const float* Wk   = (const float*)d_in[6];
    const float* bk   = (const float*)d_in[7];
    const float* Wv   = (const float*)d_in[8];
    const float* bv   = (const float*)d_in[9];
    const float* Wo   = (const float*)d_in[10];
    const float* bo   = (const float*)d_in[11];

    float* out = (float*)d_out;
    float* sc  = out + (size_t)Bb * Sq * Dm;   // scores_out region

    // attn smem: Qs 256*68 + Ks 2*64*68 + Vs 2*64*72 + Ps 256*68 words
    const int attn_smem = (256 * 68 + 2 * 64 * 68 + 2 * 64 * 72 + 256 * 68) * 4; // 210944
    cudaFuncSetAttribute(attn_fused, cudaFuncAttributeMaxDynamicSharedMemorySize, attn_smem);

    dim3 gp(Dm / 128, (Bb * Sq) / 128, 3);
    proj_tc<<<gp, 256>>>(q, k, v, Wq, Wk, Wv, bq, bk, bv);

    dim3 ga(Sq / QT, Bb * Hh);
    attn_fused<<<ga, 512, attn_smem>>>(mask, sc);

    float* linv_ptr;
    cudaGetSymbolAddress((void**)&linv_ptr, g_linv);
    norm_rows<<<Bb * Sq * Hh, 512>>>(sc, linv_ptr);

    dim3 go(Dm / 128, (Bb * Sq) / 128);
    outproj_tc<<<go, 256>>>(Wo, bo, out);
}

// round 7
// speedup vs baseline: 1.5986x; 1.1146x over previous
#include <cuda_runtime.h>
#include <cstdint>

#define Bb 2
#define Sq 2048
#define Dm 1024
#define Hh 16
#define Dk 64

// Scratch (allocation-free rule: __device__ globals)
__device__ __align__(16) float g_qh[(size_t)Bb*Hh*Sq*Dk];
__device__ __align__(16) float g_kh[(size_t)Bb*Hh*Sq*Dk];
__device__ __align__(16) float g_vh[(size_t)Bb*Hh*Sq*Dk];
__device__ __align__(16) float g_ao[(size_t)Bb*Sq*Dm];
__device__ __align__(16) float g_linv[(size_t)Bb*Sq*Hh];

// ---------------------------------------------------------------------------
__device__ __forceinline__ uint32_t f2tf(float x) {
    uint32_t u;
    asm("cvt.rna.tf32.f32 %0, %1;" : "=r"(u) : "f"(x));
    return u;
}

__device__ __forceinline__ void mma_tf32(float c[4],
    uint32_t a0, uint32_t a1, uint32_t a2, uint32_t a3,
    uint32_t b0, uint32_t b1)
{
    asm volatile(
        "mma.sync.aligned.m16n8k8.row.col.f32.tf32.tf32.f32 "
        "{%0,%1,%2,%3}, {%4,%5,%6,%7}, {%8,%9}, {%0,%1,%2,%3};"
        : "+f"(c[0]), "+f"(c[1]), "+f"(c[2]), "+f"(c[3])
        : "r"(a0), "r"(a1), "r"(a2), "r"(a3), "r"(b0), "r"(b1));
}

__device__ __forceinline__ uint4 tf4(float4 v) {
    uint4 u;
    u.x = f2tf(v.x); u.y = f2tf(v.y); u.z = f2tf(v.z); u.w = f2tf(v.w);
    return u;
}

__device__ __forceinline__ void ldsm_x4(uint32_t& r0, uint32_t& r1,
                                        uint32_t& r2, uint32_t& r3, uint32_t addr)
{
    asm volatile("ldmatrix.sync.aligned.m8n8.x4.shared.b16 {%0,%1,%2,%3}, [%4];"
        : "=r"(r0), "=r"(r1), "=r"(r2), "=r"(r3) : "r"(addr));
}

__device__ __forceinline__ uint32_t s2u(const void* p) {
    return (uint32_t)__cvta_generic_to_shared(p);
}

// ============================================================================
// K1: fused Q/K/V projection (tf32 MMA, reg double-buffer, ldmatrix frags).
// 128x128 block, BK=16, 8 warps 2(m) x 4(n), warp tile 64x32.
// ============================================================================
__global__ __launch_bounds__(256) void proj_tc(
    const float* __restrict__ xq, const float* __restrict__ xk, const float* __restrict__ xv,
    const float* __restrict__ wq, const float* __restrict__ wk, const float* __restrict__ wv,
    const float* __restrict__ bq, const float* __restrict__ bk, const float* __restrict__ bv)
{
    const int which = blockIdx.z;
    const float* __restrict__ A    = which == 0 ? xq : (which == 1 ? xk : xv);
    const float* __restrict__ W    = which == 0 ? wq : (which == 1 ? wk : wv);
    const float* __restrict__ bias = which == 0 ? bq : (which == 1 ? bk : bv);
    float* __restrict__ dst        = which == 0 ? g_qh : (which == 1 ? g_kh : g_vh);

    __shared__ uint32_t As[2][128][20];   // [st][row m][k], tf32
    __shared__ uint32_t Bs[2][128][20];   // [st][row n][k]

    const int tid = threadIdx.x;
    const int lane = tid & 31, wid = tid >> 5;
    const int wm = wid & 1, wn = wid >> 1;
    const int bm = blockIdx.y * 128, bn = blockIdx.x * 128;
    const int lr = lane >> 2, lc = lane & 3;

    const int row0 = tid >> 2,          kq0 = (tid & 3) << 2;
    const int row1 = (tid + 256) >> 2,  kq1 = ((tid + 256) & 3) << 2;

    // ldmatrix lane->row/col mapping (A: 16x8 block as 4 8x4-b32 matrices;
    // B: 16 n-rows x 8 k as 4 matrices)
    const int a_r = (lane & 7) + ((lane >> 3) & 1) * 8;
    const int a_c = ((lane >> 4) & 1) * 4;
    const int b_sel = lane >> 3;
    const int b_r = ((b_sel >> 1) & 1) * 8 + (lane & 7);
    const int b_c = (b_sel & 1) * 4;

    const uint32_t sA = s2u(&As[0][0][0]);
    const uint32_t sB = s2u(&Bs[0][0][0]);

    float4 ra0, ra1, rb0, rb1;

#define PJ_LD(k0) do { \
    ra0 = *(const float4*)(A + (size_t)(bm + row0) * Dm + (k0) + kq0); \
    rb0 = *(const float4*)(W + (size_t)(bn + row0) * Dm + (k0) + kq0); \
    ra1 = *(const float4*)(A + (size_t)(bm + row1) * Dm + (k0) + kq1); \
    rb1 = *(const float4*)(W + (size_t)(bn + row1) * Dm + (k0) + kq1); \
} while (0)

#define PJ_ST(st) do { \
    *(uint4*)&As[st][row0][kq0] = tf4(ra0); \
    *(uint4*)&Bs[st][row0][kq0] = tf4(rb0); \
    *(uint4*)&As[st][row1][kq1] = tf4(ra1); \
    *(uint4*)&Bs[st][row1][kq1] = tf4(rb1); \
} while (0)

    float acc[4][4][4];
#pragma unroll
    for (int i = 0; i < 4; i++)
#pragma unroll
        for (int j = 0; j < 4; j++)
#pragma unroll
            for (int t = 0; t < 4; t++) acc[i][j][t] = 0.f;

    PJ_LD(0); PJ_ST(0); __syncthreads();

    for (int it = 0; it < 64; it++) {
        const int cur = it & 1;
        if (it < 63) PJ_LD((it + 1) * 16);
#pragma unroll
        for (int ks = 0; ks < 16; ks += 8) {
            uint32_t af[4][4], bf[4][2];
#pragma unroll
            for (int mt = 0; mt < 4; mt++)
                ldsm_x4(af[mt][0], af[mt][1], af[mt][2], af[mt][3],
                    sA + ((cur * 128 + wm * 64 + mt * 16 + a_r) * 20 + ks + a_c) * 4);
#pragma unroll
            for (int ntp = 0; ntp < 2; ntp++)
                ldsm_x4(bf[2 * ntp][0], bf[2 * ntp][1], bf[2 * ntp + 1][0], bf[2 * ntp + 1][1],
                    sB + ((cur * 128 + wn * 32 + ntp * 16 + b_r) * 20 + ks + b_c) * 4);
#pragma unroll
            for (int mt = 0; mt < 4; mt++)
#pragma unroll
                for (int nt = 0; nt < 4; nt++)
                    mma_tf32(acc[mt][nt], af[mt][0], af[mt][1], af[mt][2], af[mt][3],
                             bf[nt][0], bf[nt][1]);
        }
        if (it < 63) PJ_ST(cur ^ 1);
        __syncthreads();
    }

#pragma unroll
    for (int mt = 0; mt < 4; mt++) {
#pragma unroll
        for (int nt = 0; nt < 4; nt++) {
            int col = bn + wn * 32 + nt * 8 + lc * 2;
            int h = col >> 6, d = col & 63;
            float b0 = bias[col], b1 = bias[col + 1];
#pragma unroll
            for (int half = 0; half < 2; half++) {
                int m = bm + wm * 64 + mt * 16 + lr + half * 8;
                int b = m >> 11;
                int s = m & (Sq - 1);
                float2 v;
                v.x = acc[mt][nt][half * 2 + 0] + b0;
                v.y = acc[mt][nt][half * 2 + 1] + b1;
                *(float2*)(dst + (((size_t)(b * Hh + h) * Sq + s) << 6) + d) = v;
            }
        }
    }
#undef PJ_LD
#undef PJ_ST
}

// ============================================================================
// K2: fused attention, single pass, no max-subtraction. Writes UNNORMALIZED
// exp(s) + 1/rowsum. 512 threads, q-tile 256, reg double-buffered K/V,
// ldmatrix fragments for Q/K/P, scalar for V.
// ============================================================================
#define QT 256

__global__ __launch_bounds__(512, 1) void attn_fused(
    const int* __restrict__ mask, float* __restrict__ sc)
{
    extern __shared__ uint32_t sh[];
    uint32_t (*Qs)[68]     = (uint32_t(*)[68])sh;                    // [q256][d]
    uint32_t (*Ks)[64][68] = (uint32_t(*)[64][68])(sh + 17408);      // [st][tok][d]
    uint32_t (*Vs)[64][72] = (uint32_t(*)[64][72])(sh + 17408 + 8704); // [st][tok][d]
    float    (*Ps)[68]     = (float(*)[68])(sh + 17408 + 8704 + 9216); // [q][k]

    const int bh = blockIdx.y;
    const int b = bh >> 4, h = bh & 15;
    const int q0 = blockIdx.x * QT;
    const float* qp    = g_qh + ((size_t)bh * Sq + q0) * Dk;
    const float* kbase = g_kh + (size_t)bh * Sq * Dk;
    const float* vbase = g_vh + (size_t)bh * Sq * Dk;

    const int tid = threadIdx.x;
    const int lane = tid & 31, w = tid >> 5;          // 16 warps
    const int lr = lane >> 2, lc = lane & 3;
    const int r0 = 16 * w + lr;                        // local q row; second = r0+8
    const int qg0 = q0 + r0;

    const int a_r = (lane & 7) + ((lane >> 3) & 1) * 8;
    const int a_c = ((lane >> 4) & 1) * 4;
    const int b_sel = lane >> 3;
    const int b_r = ((b_sel >> 1) & 1) * 8 + (lane & 7);
    const int b_c = (b_sel & 1) * 4;

    const uint32_t sK = s2u(&Ks[0][0][0]);
    const uint32_t qaddr = s2u(&Qs[16 * w + a_r][a_c]);
    const uint32_t paddr = s2u(&Ps[16 * w + a_r][a_c]);

    const int rA = tid >> 4, cA = (tid & 15) << 2;    // K/V tile: 64x64, 2 f4/thread
    const int rB = rA + 32;

    float4 rk0, rk1, rv0, rv1;

#define AT_LDK(kt) do { \
    rk0 = *(const float4*)(kbase + (size_t)((kt) + rA) * Dk + cA); \
    rk1 = *(const float4*)(kbase + (size_t)((kt) + rB) * Dk + cA); \
} while (0)
#define AT_STK(st) do { \
    *(uint4*)&Ks[st][rA][cA] = tf4(rk0); \
    *(uint4*)&Ks[st][rB][cA] = tf4(rk1); \
} while (0)
#define AT_LDV(kt) do { \
    rv0 = *(const float4*)(vbase + (size_t)((kt) + rA) * Dk + cA); \
    rv1 = *(const float4*)(vbase + (size_t)((kt) + rB) * Dk + cA); \
} while (0)
#define AT_STV(st) do { \
    *(uint4*)&Vs[st][rA][cA] = tf4(rv0); \
    *(uint4*)&Vs[st][rB][cA] = tf4(rv1); \
} while (0)

    // load Q tile -> Qs[q][d]
#pragma unroll
    for (int t = 0; t < 8; t++) {
        int f = tid + t * 512;
        int row = f >> 4;
        int c4 = (f & 15) << 2;
        *(uint4*)&Qs[row][c4] = tf4(*(const float4*)(qp + row * Dk + c4));
    }

    const int* mrow0 = mask + ((size_t)b * Sq + qg0) * Sq;
    const int* mrow1 = mrow0 + 8 * Sq;

    float lsum0 = 0.f, lsum1 = 0.f;
    float o_acc[8][4];
#pragma unroll
    for (int nt = 0; nt < 8; nt++)
#pragma unroll
        for (int e = 0; e < 4; e++) o_acc[nt][e] = 0.f;

    AT_LDK(0); AT_LDV(0); AT_STK(0); AT_STV(0); __syncthreads();

    for (int it = 0; it < Sq / 64; it++) {
        const int cur = it & 1;
        const int kt = it * 64;
        if (it < Sq / 64 - 1) { AT_LDK(kt + 64); AT_LDV(kt + 64); }

        float acc[8][4];
#pragma unroll
        for (int nt = 0; nt < 8; nt++)
#pragma unroll
            for (int e = 0; e < 4; e++) acc[nt][e] = 0.f;

        // QK^T via ldmatrix fragments
#pragma unroll
        for (int ks = 0; ks < 64; ks += 8) {
            uint32_t qa[4], kb[8][2];
            ldsm_x4(qa[0], qa[1], qa[2], qa[3], qaddr + ks * 4);
#pragma unroll
            for (int ntp = 0; ntp < 4; ntp++)
                ldsm_x4(kb[2 * ntp][0], kb[2 * ntp][1], kb[2 * ntp + 1][0], kb[2 * ntp + 1][1],
                    sK + ((cur * 64 + ntp * 16 + b_r) * 68 + ks + b_c) * 4);
#pragma unroll
            for (int nt = 0; nt < 8; nt++)
                mma_tf32(acc[nt], qa[0], qa[1], qa[2], qa[3], kb[nt][0], kb[nt][1]);
        }

        // exp (no max), mask -> 0, accumulate row sums, stage into Ps
#pragma unroll
        for (int nt = 0; nt < 8; nt++) {
            int kc = kt + nt * 8 + lc * 2;
            int2 ma = *(const int2*)(mrow0 + kc);
            int2 mb = *(const int2*)(mrow1 + kc);
            float e00 = (ma.x == 0) ? 0.f : __expf(acc[nt][0] * 0.125f);
            float e01 = (ma.y == 0) ? 0.f : __expf(acc[nt][1] * 0.125f);
            float e10 = (mb.x == 0) ? 0.f : __expf(acc[nt][2] * 0.125f);
            float e11 = (mb.y == 0) ? 0.f : __expf(acc[nt][3] * 0.125f);
            lsum0 += e00 + e01;
            lsum1 += e10 + e11;
            int cl = nt * 8 + lc * 2;
            Ps[r0][cl]         = e00;
            Ps[r0][cl + 1]     = e01;
            Ps[r0 + 8][cl]     = e10;
            Ps[r0 + 8][cl + 1] = e11;
        }
        __syncthreads();

        // coalesced write of unnormalized E tile (256 rows x 64 cols)
#pragma unroll
        for (int t = 0; t < 8; t++) {
            int f = tid + t * 512;
            int row = f >> 4;
            int c4 = (f & 15) << 2;
            float4 v = *(const float4*)&Ps[row][c4];
            *(float4*)(sc + (((size_t)(b * Sq + q0 + row)) * Hh + h) * Sq + kt + c4) = v;
        }

        // O += E @ V  (E raw fp32 bits -> HW tf32 truncation; V cvt'd in smem)
#pragma unroll
        for (int ks = 0; ks < 64; ks += 8) {
            uint32_t pa[4];
            ldsm_x4(pa[0], pa[1], pa[2], pa[3], paddr + ks * 4);
#pragma unroll
            for (int nt = 0; nt < 8; nt++) {
                uint32_t b0 = Vs[cur][ks + lc][nt * 8 + lr];
                uint32_t b1 = Vs[cur][ks + 4 + lc][nt * 8 + lr];
                mma_tf32(o_acc[nt], pa[0], pa[1], pa[2], pa[3], b0, b1);
            }
        }

        if (it < Sq / 64 - 1) { AT_STK(cur ^ 1); AT_STV(cur ^ 1); }
        __syncthreads();
    }

    // reduce row sums over the 4 lc lanes
    lsum0 += __shfl_xor_sync(0xffffffffu, lsum0, 1);
    lsum0 += __shfl_xor_sync(0xffffffffu, lsum0, 2);
    lsum1 += __shfl_xor_sync(0xffffffffu, lsum1, 1);
    lsum1 += __shfl_xor_sync(0xffffffffu, lsum1, 2);
    const float inv0 = 1.0f / lsum0, inv1 = 1.0f / lsum1;

    if (lc == 0) {
        g_linv[((size_t)(b * Sq + qg0)) * Hh + h]     = inv0;
        g_linv[((size_t)(b * Sq + qg0 + 8)) * Hh + h] = inv1;
    }

    // epilogue: write O (scaled) to g_ao in (b,s,D) layout
    float* orow0 = g_ao + (size_t)(b * Sq + qg0) * Dm + h * Dk;
    float* orow1 = orow0 + 8 * Dm;
#pragma unroll
    for (int nt = 0; nt < 8; nt++) {
        int d = nt * 8 + lc * 2;
        *(float2*)(orow0 + d) = make_float2(o_acc[nt][0] * inv0, o_acc[nt][1] * inv0);
        *(float2*)(orow1 + d) = make_float2(o_acc[nt][2] * inv1, o_acc[nt][3] * inv1);
    }
#undef AT_LDK
#undef AT_STK
#undef AT_LDV
#undef AT_STV
}

// ============================================================================
// K3: normalize scores rows: sc[row][:] *= linv[row]. Pure streaming.
// ============================================================================
__global__ __launch_bounds__(512) void norm_rows(
    float* __restrict__ sc, const float* __restrict__ linv)
{
    const int r = blockIdx.x;
    const float s = linv[r];
    float4* p = (float4*)(sc + (size_t)r * Sq);
    float4 v = p[threadIdx.x];
    v.x *= s; v.y *= s; v.z *= s; v.w *= s;
    p[threadIdx.x] = v;
}

// ============================================================================
// K4: final projection out = g_ao @ Wo^T + bo  (tf32 MMA, ldmatrix frags)
// ============================================================================
__global__ __launch_bounds__(256) void outproj_tc(
    const float* __restrict__ W, const float* __restrict__ bias, float* __restrict__ C)
{
    __shared__ uint32_t As[2][128][20];
    __shared__ uint32_t Bs[2][128][20];
    const int tid = threadIdx.x;
    const int lane = tid & 31, wid = tid >> 5;
    const int wm = wid & 1, wn = wid >> 1;
    const int bm = blockIdx.y * 128, bn = blockIdx.x * 128;
    const int lr = lane >> 2, lc = lane & 3;
    const float* __restrict__ A = g_ao;

    const int row0 = tid >> 2,          kq0 = (tid & 3) << 2;
    const int row1 = (tid + 256) >> 2,  kq1 = ((tid + 256) & 3) << 2;

    const int a_r = (lane & 7) + ((lane >> 3) & 1) * 8;
    const int a_c = ((lane >> 4) & 1) * 4;
    const int b_sel = lane >> 3;
    const int b_r = ((b_sel >> 1) & 1) * 8 + (lane & 7);
    const int b_c = (b_sel & 1) * 4;

    const uint32_t sA = s2u(&As[0][0][0]);
    const uint32_t sB = s2u(&Bs[0][0][0]);

    float4 ra0, ra1, rb0, rb1;

#define OP_LD(k0) do { \
    ra0 = *(const float4*)(A + (size_t)(bm + row0) * Dm + (k0) + kq0); \
    rb0 = *(const float4*)(W + (size_t)(bn + row0) * Dm + (k0) + kq0); \
    ra1 = *(const float4*)(A + (size_t)(bm + row1) * Dm + (k0) + kq1); \
    rb1 = *(const float4*)(W + (size_t)(bn + row1) * Dm + (k0) + kq1); \
} while (0)

#define OP_ST(st) do { \
    *(uint4*)&As[st][row0][kq0] = tf4(ra0); \
    *(uint4*)&Bs[st][row0][kq0] = tf4(rb0); \
    *(uint4*)&As[st][row1][kq1] = tf4(ra1); \
    *(uint4*)&Bs[st][row1][kq1] = tf4(rb1); \
} while (0)

    float acc[4][4][4];
#pragma unroll
    for (int i = 0; i < 4; i++)
#pragma unroll
        for (int j = 0; j < 4; j++)
#pragma unroll
            for (int t = 0; t < 4; t++) acc[i][j][t] = 0.f;

    OP_LD(0); OP_ST(0); __syncthreads();

    for (int it = 0; it < 64; it++) {
        const int cur = it & 1;
        if (it < 63) OP_LD((it + 1) * 16);
#pragma unroll
        for (int ks = 0; ks < 16; ks += 8) {
            uint32_t af[4][4], bf[4][2];
#pragma unroll
            for (int mt = 0; mt < 4; mt++)
                ldsm_x4(af[mt][0], af[mt][1], af[mt][2], af[mt][3],
                    sA + ((cur * 128 + wm * 64 + mt * 16 + a_r) * 20 + ks + a_c) * 4);
#pragma unroll
            for (int ntp = 0; ntp < 2; ntp++)
                ldsm_x4(bf[2 * ntp][0], bf[2 * ntp][1], bf[2 * ntp + 1][0], bf[2 * ntp + 1][1],
                    sB + ((cur * 128 + wn * 32 + ntp * 16 + b_r) * 20 + ks + b_c) * 4);
#pragma unroll
            for (int mt = 0; mt < 4; mt++)
#pragma unroll
                for (int nt = 0; nt < 4; nt++)
                    mma_tf32(acc[mt][nt], af[mt][0], af[mt][1], af[mt][2], af[mt][3],
                             bf[nt][0], bf[nt][1]);
        }
        if (it < 63) OP_ST(cur ^ 1);
        __syncthreads();
    }

#pragma unroll
    for (int mt = 0; mt < 4; mt++) {
#pragma unroll
        for (int nt = 0; nt < 4; nt++) {
            int col = bn + wn * 32 + nt * 8 + lc * 2;
            float b0 = bias[col], b1 = bias[col + 1];
#pragma unroll
            for (int half = 0; half < 2; half++) {
                int m = bm + wm * 64 + mt * 16 + lr + half * 8;
                float2 v;
                v.x = acc[mt][nt][half * 2 + 0] + b0;
                v.y = acc[mt][nt][half * 2 + 1] + b1;
                *(float2*)(C + (size_t)m * Dm + col) = v;
            }
        }
    }
#undef OP_LD
#undef OP_ST
}

// ============================================================================
extern "C" void kernel_launch(void* const* d_in, const int* in_sizes, int n_in,
                              void* d_out, int out_size)
{
    const float* q    = (const float*)d_in[0];
    const float* k    = (const float*)d_in[1];
    const float* v    = (const float*)d_in[2];
    const int*   mask = (const int*)d_in[3];
    const float* Wq   = (const float*)d_in[4];
    const float* bq   = (const float*)d_in[5];
    const float* Wk   = (const float*)d_in[6];
    const float* bk   = (const float*)d_in[7];
    const float* Wv   = (const float*)d_in[8];
    const float* bv   = (const float*)d_in[9];
    const float* Wo   = (const float*)d_in[10];
    const float* bo   = (const float*)d_in[11];

    float* out = (float*)d_out;
    float* sc  = out + (size_t)Bb * Sq * Dm;   // scores_out region

    // attn smem: Qs 256*68 + Ks 2*64*68 + Vs 2*64*72 + Ps 256*68 words
    const int attn_smem = (256 * 68 + 2 * 64 * 68 + 2 * 64 * 72 + 256 * 68) * 4; // 210944
    cudaFuncSetAttribute(attn_fused, cudaFuncAttributeMaxDynamicSharedMemorySize, attn_smem);

    dim3 gp(Dm / 128, (Bb * Sq) / 128, 3);
    proj_tc<<<gp, 256>>>(q, k, v, Wq, Wk, Wv, bq, bk, bv);

    dim3 ga(Sq / QT, Bb * Hh);
    attn_fused<<<ga, 512, attn_smem>>>(mask, sc);

    float* linv_ptr;
    cudaGetSymbolAddress((void**)&linv_ptr, g_linv);
    norm_rows<<<Bb * Sq * Hh, 512>>>(sc, linv_ptr);

    dim3 go(Dm / 128, (Bb * Sq) / 128);
    outproj_tc<<<go, 256>>>(Wo, bo, out);
}